// round 1
// baseline (speedup 1.0000x reference)
#include <cuda_runtime.h>

#define BQ 8
#define LQ 8192
#define DQ 256

// Scratch (device globals; no allocation allowed in kernel_launch)
__device__ float g_kvs[BQ * DQ * DQ];   // [b][m][d]  2 MB
__device__ float g_ksum[BQ * DQ];       // [b][m]
__device__ float g_norm[BQ * LQ];       // [b][l]

__device__ __forceinline__ float relu_eps(float x) { return fmaxf(x, 0.0f) + 1e-3f; }

// Packed fp32x2 helpers (FFMA2 path — 2x scalar FFMA throughput on Blackwell)
__device__ __forceinline__ unsigned long long pack2(float lo, float hi) {
    unsigned long long r;
    asm("mov.b64 %0, {%1, %2};" : "=l"(r) : "f"(lo), "f"(hi));
    return r;
}
__device__ __forceinline__ void unpack2(unsigned long long v, float& lo, float& hi) {
    asm("mov.b64 {%0, %1}, %2;" : "=f"(lo), "=f"(hi) : "l"(v));
}
__device__ __forceinline__ unsigned long long fma2(unsigned long long a,
                                                   unsigned long long b,
                                                   unsigned long long c) {
    unsigned long long d;
    asm("fma.rn.f32x2 %0, %1, %2, %3;" : "=l"(d) : "l"(a), "l"(b), "l"(c));
    return d;
}

// ---------------------------------------------------------------------------
// Kernel 1: zero the accumulated scratch (kvs + ksum)
// ---------------------------------------------------------------------------
__global__ void zero_kernel() {
    int i = blockIdx.x * 256 + threadIdx.x;
    if (i < BQ * DQ * DQ) g_kvs[i] = 0.0f;
    if (i < BQ * DQ) g_ksum[i] = 0.0f;
}

// ---------------------------------------------------------------------------
// Kernel 2: k_sum[b][m] = sum_l relu_eps(K[b][l][m])
// grid (32 l-chunks, B), 256 threads (thread = one m). Coalesced across m.
// ---------------------------------------------------------------------------
__global__ void __launch_bounds__(256) ksum_kernel(const float* __restrict__ keys) {
    int b = blockIdx.y;
    int m = threadIdx.x;
    const float* kp = keys + ((size_t)b * LQ + (size_t)blockIdx.x * 256) * DQ + m;
    float s = 0.0f;
#pragma unroll 8
    for (int l = 0; l < 256; l++) s += relu_eps(kp[(size_t)l * DQ]);
    atomicAdd(&g_ksum[b * DQ + m], s);
}

// ---------------------------------------------------------------------------
// Kernel 3: kvs[b][m][d] += sum_{l in chunk} relu_eps(K[b][l][m]) * V[b][l][d]
// grid (16 = 4 m-tiles x 4 d-tiles, 4 l-chunks, B), 256 threads.
// 64x64 output tile, 4x4 per thread as 8 packed fma2.
// ---------------------------------------------------------------------------
__global__ void __launch_bounds__(256) kvs_kernel(const float* __restrict__ keys,
                                                  const float* __restrict__ values) {
    __shared__ float Ks[16][68];
    __shared__ float Vs[16][68];

    const int b = blockIdx.z;
    const int m0 = (blockIdx.x >> 2) * 64;
    const int d0 = (blockIdx.x & 3) * 64;
    const int l0base = blockIdx.y * (LQ / 4);

    const int t = threadIdx.x;
    const int tx = t & 15;         // d direction (4 cols)
    const int ty = t >> 4;         // m direction (4 rows)
    const int lrow = t >> 4;       // load: row within 16-L step
    const int lcol = (t & 15) * 4; // load: 4 consecutive elements

    unsigned long long acc[4][2];
#pragma unroll
    for (int r = 0; r < 4; r++) { acc[r][0] = 0ull; acc[r][1] = 0ull; }

    const float* kbase = keys + (size_t)b * LQ * DQ + m0;
    const float* vbase = values + (size_t)b * LQ * DQ + d0;

    for (int l0 = l0base; l0 < l0base + LQ / 4; l0 += 16) {
        float4 k4 = *(const float4*)(kbase + (size_t)(l0 + lrow) * DQ + lcol);
        float4 v4 = *(const float4*)(vbase + (size_t)(l0 + lrow) * DQ + lcol);
        __syncthreads();
        float4 kr;
        kr.x = relu_eps(k4.x); kr.y = relu_eps(k4.y);
        kr.z = relu_eps(k4.z); kr.w = relu_eps(k4.w);
        *(float4*)&Ks[lrow][lcol] = kr;
        *(float4*)&Vs[lrow][lcol] = v4;
        __syncthreads();
#pragma unroll
        for (int kk = 0; kk < 16; kk++) {
            float4 a = *(const float4*)&Ks[kk][ty * 4];
            unsigned long long b0 = *(const unsigned long long*)&Vs[kk][tx * 4];
            unsigned long long b1 = *(const unsigned long long*)&Vs[kk][tx * 4 + 2];
            unsigned long long av;
            av = pack2(a.x, a.x);
            acc[0][0] = fma2(av, b0, acc[0][0]); acc[0][1] = fma2(av, b1, acc[0][1]);
            av = pack2(a.y, a.y);
            acc[1][0] = fma2(av, b0, acc[1][0]); acc[1][1] = fma2(av, b1, acc[1][1]);
            av = pack2(a.z, a.z);
            acc[2][0] = fma2(av, b0, acc[2][0]); acc[2][1] = fma2(av, b1, acc[2][1]);
            av = pack2(a.w, a.w);
            acc[3][0] = fma2(av, b0, acc[3][0]); acc[3][1] = fma2(av, b1, acc[3][1]);
        }
    }

    float* outp = g_kvs + ((size_t)b * DQ + m0 + ty * 4) * DQ + d0 + tx * 4;
#pragma unroll
    for (int r = 0; r < 4; r++) {
        float v0, v1, v2, v3;
        unpack2(acc[r][0], v0, v1);
        unpack2(acc[r][1], v2, v3);
        atomicAdd(&outp[(size_t)r * DQ + 0], v0);
        atomicAdd(&outp[(size_t)r * DQ + 1], v1);
        atomicAdd(&outp[(size_t)r * DQ + 2], v2);
        atomicAdd(&outp[(size_t)r * DQ + 3], v3);
    }
}

// ---------------------------------------------------------------------------
// Kernel 4: norm[b][l] = sum_m relu_eps(Q[b][l][m]) * ksum[b][m]
// One warp per row; coalesced 128B reads; shfl reduce.
// grid (L/8, B), 256 threads (8 warps).
// ---------------------------------------------------------------------------
__global__ void __launch_bounds__(256) norm_kernel(const float* __restrict__ queries) {
    int b = blockIdx.y;
    int warp = threadIdx.x >> 5;
    int lane = threadIdx.x & 31;
    int l = blockIdx.x * 8 + warp;
    const float* qp = queries + ((size_t)b * LQ + l) * DQ;
    const float* ks = g_ksum + b * DQ;
    float s = 0.0f;
#pragma unroll
    for (int m = lane; m < DQ; m += 32) s += relu_eps(qp[m]) * ks[m];
#pragma unroll
    for (int o = 16; o > 0; o >>= 1) s += __shfl_xor_sync(0xffffffffu, s, o);
    if (lane == 0) g_norm[b * LQ + l] = s;
}

// ---------------------------------------------------------------------------
// Kernel 5: out[b][l][d] = (sum_m relu_eps(Q[b][l][m]) * kvs[b][m][d]) / norm[b][l]
// grid (L/64, 4 d-tiles, B), 256 threads. 64x64 tile, K = 256.
// ---------------------------------------------------------------------------
__global__ void __launch_bounds__(256) out_kernel(const float* __restrict__ queries,
                                                  float* __restrict__ out) {
    __shared__ float Qs[64][17];
    __shared__ float KVs[16][68];

    const int b = blockIdx.z;
    const int l0 = blockIdx.x * 64;
    const int d0 = blockIdx.y * 64;

    const int t = threadIdx.x;
    const int tx = t & 15;  // d direction
    const int ty = t >> 4;  // l direction

    const int qrow = t >> 2;          // 0..63
    const int qcol = (t & 3) * 4;     // 0..12
    const int krow = t >> 4;          // 0..15
    const int kcol = (t & 15) * 4;    // 0..60

    unsigned long long acc[4][2];
#pragma unroll
    for (int r = 0; r < 4; r++) { acc[r][0] = 0ull; acc[r][1] = 0ull; }

    const float* qbase = queries + ((size_t)b * LQ + l0) * DQ;
    const float* kvbase = g_kvs + (size_t)b * DQ * DQ + d0;

    for (int ms = 0; ms < DQ; ms += 16) {
        float4 q4 = *(const float4*)(qbase + (size_t)qrow * DQ + ms + qcol);
        float4 kv4 = *(const float4*)(kvbase + (size_t)(ms + krow) * DQ + kcol);
        __syncthreads();
        Qs[qrow][qcol + 0] = relu_eps(q4.x);
        Qs[qrow][qcol + 1] = relu_eps(q4.y);
        Qs[qrow][qcol + 2] = relu_eps(q4.z);
        Qs[qrow][qcol + 3] = relu_eps(q4.w);
        *(float4*)&KVs[krow][kcol] = kv4;
        __syncthreads();
#pragma unroll
        for (int kk = 0; kk < 16; kk++) {
            float a0 = Qs[ty * 4 + 0][kk];
            float a1 = Qs[ty * 4 + 1][kk];
            float a2 = Qs[ty * 4 + 2][kk];
            float a3 = Qs[ty * 4 + 3][kk];
            unsigned long long b0 = *(const unsigned long long*)&KVs[kk][tx * 4];
            unsigned long long b1 = *(const unsigned long long*)&KVs[kk][tx * 4 + 2];
            unsigned long long av;
            av = pack2(a0, a0);
            acc[0][0] = fma2(av, b0, acc[0][0]); acc[0][1] = fma2(av, b1, acc[0][1]);
            av = pack2(a1, a1);
            acc[1][0] = fma2(av, b0, acc[1][0]); acc[1][1] = fma2(av, b1, acc[1][1]);
            av = pack2(a2, a2);
            acc[2][0] = fma2(av, b0, acc[2][0]); acc[2][1] = fma2(av, b1, acc[2][1]);
            av = pack2(a3, a3);
            acc[3][0] = fma2(av, b0, acc[3][0]); acc[3][1] = fma2(av, b1, acc[3][1]);
        }
    }

    float* op = out + ((size_t)b * LQ + l0 + ty * 4) * DQ + d0 + tx * 4;
#pragma unroll
    for (int r = 0; r < 4; r++) {
        float inv = 1.0f / g_norm[b * LQ + l0 + ty * 4 + r];
        float v0, v1, v2, v3;
        unpack2(acc[r][0], v0, v1);
        unpack2(acc[r][1], v2, v3);
        op[(size_t)r * DQ + 0] = v0 * inv;
        op[(size_t)r * DQ + 1] = v1 * inv;
        op[(size_t)r * DQ + 2] = v2 * inv;
        op[(size_t)r * DQ + 3] = v3 * inv;
    }
}

// ---------------------------------------------------------------------------
extern "C" void kernel_launch(void* const* d_in, const int* in_sizes, int n_in,
                              void* d_out, int out_size) {
    const float* queries = (const float*)d_in[0];
    const float* keys    = (const float*)d_in[1];
    const float* values  = (const float*)d_in[2];
    float* out = (float*)d_out;

    zero_kernel<<<(BQ * DQ * DQ + 255) / 256, 256>>>();
    ksum_kernel<<<dim3(32, BQ), 256>>>(keys);
    kvs_kernel<<<dim3(16, 4, BQ), 256>>>(keys, values);
    norm_kernel<<<dim3(LQ / 8, BQ), 256>>>(queries);
    out_kernel<<<dim3(LQ / 64, 4, BQ), 256>>>(queries, out);
}

// round 2
// speedup vs baseline: 1.0045x; 1.0045x over previous
#include <cuda_runtime.h>

#define BQ 8
#define LQ 8192
#define DQ 256

// Scratch (device globals; no allocation allowed in kernel_launch)
__device__ float g_kvs[BQ * DQ * DQ];   // [b][m][d]  2 MB
__device__ float g_ksum[BQ * DQ];       // [b][m]
__device__ float g_norm[BQ * LQ];       // [b][l]

__device__ __forceinline__ float relu_eps(float x) { return fmaxf(x, 0.0f) + 1e-3f; }

// Packed fp32x2 helpers (FFMA2 path — 2x scalar FFMA throughput on Blackwell)
__device__ __forceinline__ unsigned long long pack2(float lo, float hi) {
    unsigned long long r;
    asm("mov.b64 %0, {%1, %2};" : "=l"(r) : "f"(lo), "f"(hi));
    return r;
}
__device__ __forceinline__ void unpack2(unsigned long long v, float& lo, float& hi) {
    asm("mov.b64 {%0, %1}, %2;" : "=f"(lo), "=f"(hi) : "l"(v));
}
__device__ __forceinline__ unsigned long long fma2(unsigned long long a,
                                                   unsigned long long b,
                                                   unsigned long long c) {
    unsigned long long d;
    asm("fma.rn.f32x2 %0, %1, %2, %3;" : "=l"(d) : "l"(a), "l"(b), "l"(c));
    return d;
}

// ---------------------------------------------------------------------------
// Kernel 1: zero the accumulated scratch (kvs + ksum)
// ---------------------------------------------------------------------------
__global__ void zero_kernel() {
    int i = blockIdx.x * 256 + threadIdx.x;
    if (i < BQ * DQ * DQ) g_kvs[i] = 0.0f;
    if (i < BQ * DQ) g_ksum[i] = 0.0f;
}

// ---------------------------------------------------------------------------
// Kernel 2: k_sum[b][m] = sum_l relu_eps(K[b][l][m])
// grid (32 l-chunks, B), 256 threads (thread = one m). Coalesced across m.
// ---------------------------------------------------------------------------
__global__ void __launch_bounds__(256) ksum_kernel(const float* __restrict__ keys) {
    int b = blockIdx.y;
    int m = threadIdx.x;
    const float* kp = keys + ((size_t)b * LQ + (size_t)blockIdx.x * 256) * DQ + m;
    float s = 0.0f;
#pragma unroll 8
    for (int l = 0; l < 256; l++) s += relu_eps(kp[(size_t)l * DQ]);
    atomicAdd(&g_ksum[b * DQ + m], s);
}

// ---------------------------------------------------------------------------
// Kernel 3: kvs[b][m][d] += sum_{l in chunk} relu_eps(K[b][l][m]) * V[b][l][d]
// grid (16 = 4 m-tiles x 4 d-tiles, 4 l-chunks, B), 256 threads.
// 64x64 output tile, 4x4 per thread as 8 packed fma2.
// ---------------------------------------------------------------------------
__global__ void __launch_bounds__(256) kvs_kernel(const float* __restrict__ keys,
                                                  const float* __restrict__ values) {
    __shared__ float Ks[16][68];
    __shared__ float Vs[16][68];

    const int b = blockIdx.z;
    const int m0 = (blockIdx.x >> 2) * 64;
    const int d0 = (blockIdx.x & 3) * 64;
    const int l0base = blockIdx.y * (LQ / 4);

    const int t = threadIdx.x;
    const int tx = t & 15;         // d direction (4 cols)
    const int ty = t >> 4;         // m direction (4 rows)
    const int lrow = t >> 4;       // load: row within 16-L step
    const int lcol = (t & 15) * 4; // load: 4 consecutive elements

    unsigned long long acc[4][2];
#pragma unroll
    for (int r = 0; r < 4; r++) { acc[r][0] = 0ull; acc[r][1] = 0ull; }

    const float* kbase = keys + (size_t)b * LQ * DQ + m0;
    const float* vbase = values + (size_t)b * LQ * DQ + d0;

    for (int l0 = l0base; l0 < l0base + LQ / 4; l0 += 16) {
        float4 k4 = *(const float4*)(kbase + (size_t)(l0 + lrow) * DQ + lcol);
        float4 v4 = *(const float4*)(vbase + (size_t)(l0 + lrow) * DQ + lcol);
        __syncthreads();
        float4 kr;
        kr.x = relu_eps(k4.x); kr.y = relu_eps(k4.y);
        kr.z = relu_eps(k4.z); kr.w = relu_eps(k4.w);
        *(float4*)&Ks[lrow][lcol] = kr;
        *(float4*)&Vs[lrow][lcol] = v4;
        __syncthreads();
#pragma unroll
        for (int kk = 0; kk < 16; kk++) {
            float4 a = *(const float4*)&Ks[kk][ty * 4];
            unsigned long long b0 = *(const unsigned long long*)&Vs[kk][tx * 4];
            unsigned long long b1 = *(const unsigned long long*)&Vs[kk][tx * 4 + 2];
            unsigned long long av;
            av = pack2(a.x, a.x);
            acc[0][0] = fma2(av, b0, acc[0][0]); acc[0][1] = fma2(av, b1, acc[0][1]);
            av = pack2(a.y, a.y);
            acc[1][0] = fma2(av, b0, acc[1][0]); acc[1][1] = fma2(av, b1, acc[1][1]);
            av = pack2(a.z, a.z);
            acc[2][0] = fma2(av, b0, acc[2][0]); acc[2][1] = fma2(av, b1, acc[2][1]);
            av = pack2(a.w, a.w);
            acc[3][0] = fma2(av, b0, acc[3][0]); acc[3][1] = fma2(av, b1, acc[3][1]);
        }
    }

    float* outp = g_kvs + ((size_t)b * DQ + m0 + ty * 4) * DQ + d0 + tx * 4;
#pragma unroll
    for (int r = 0; r < 4; r++) {
        float v0, v1, v2, v3;
        unpack2(acc[r][0], v0, v1);
        unpack2(acc[r][1], v2, v3);
        atomicAdd(&outp[(size_t)r * DQ + 0], v0);
        atomicAdd(&outp[(size_t)r * DQ + 1], v1);
        atomicAdd(&outp[(size_t)r * DQ + 2], v2);
        atomicAdd(&outp[(size_t)r * DQ + 3], v3);
    }
}

// ---------------------------------------------------------------------------
// Kernel 4: norm[b][l] = sum_m relu_eps(Q[b][l][m]) * ksum[b][m]
// One warp per row; coalesced 128B reads; shfl reduce.
// grid (L/8, B), 256 threads (8 warps).
// ---------------------------------------------------------------------------
__global__ void __launch_bounds__(256) norm_kernel(const float* __restrict__ queries) {
    int b = blockIdx.y;
    int warp = threadIdx.x >> 5;
    int lane = threadIdx.x & 31;
    int l = blockIdx.x * 8 + warp;
    const float* qp = queries + ((size_t)b * LQ + l) * DQ;
    const float* ks = g_ksum + b * DQ;
    float s = 0.0f;
#pragma unroll
    for (int m = lane; m < DQ; m += 32) s += relu_eps(qp[m]) * ks[m];
#pragma unroll
    for (int o = 16; o > 0; o >>= 1) s += __shfl_xor_sync(0xffffffffu, s, o);
    if (lane == 0) g_norm[b * LQ + l] = s;
}

// ---------------------------------------------------------------------------
// Kernel 5: out[b][l][d] = (sum_m relu_eps(Q[b][l][m]) * kvs[b][m][d]) / norm[b][l]
// grid (L/64, 4 d-tiles, B), 256 threads. 64x64 tile, K = 256.
// ---------------------------------------------------------------------------
__global__ void __launch_bounds__(256) out_kernel(const float* __restrict__ queries,
                                                  float* __restrict__ out) {
    __shared__ float Qs[64][17];
    __shared__ float KVs[16][68];

    const int b = blockIdx.z;
    const int l0 = blockIdx.x * 64;
    const int d0 = blockIdx.y * 64;

    const int t = threadIdx.x;
    const int tx = t & 15;  // d direction
    const int ty = t >> 4;  // l direction

    const int qrow = t >> 2;          // 0..63
    const int qcol = (t & 3) * 4;     // 0..12
    const int krow = t >> 4;          // 0..15
    const int kcol = (t & 15) * 4;    // 0..60

    unsigned long long acc[4][2];
#pragma unroll
    for (int r = 0; r < 4; r++) { acc[r][0] = 0ull; acc[r][1] = 0ull; }

    const float* qbase = queries + ((size_t)b * LQ + l0) * DQ;
    const float* kvbase = g_kvs + (size_t)b * DQ * DQ + d0;

    for (int ms = 0; ms < DQ; ms += 16) {
        float4 q4 = *(const float4*)(qbase + (size_t)qrow * DQ + ms + qcol);
        float4 kv4 = *(const float4*)(kvbase + (size_t)(ms + krow) * DQ + kcol);
        __syncthreads();
        Qs[qrow][qcol + 0] = relu_eps(q4.x);
        Qs[qrow][qcol + 1] = relu_eps(q4.y);
        Qs[qrow][qcol + 2] = relu_eps(q4.z);
        Qs[qrow][qcol + 3] = relu_eps(q4.w);
        *(float4*)&KVs[krow][kcol] = kv4;
        __syncthreads();
#pragma unroll
        for (int kk = 0; kk < 16; kk++) {
            float a0 = Qs[ty * 4 + 0][kk];
            float a1 = Qs[ty * 4 + 1][kk];
            float a2 = Qs[ty * 4 + 2][kk];
            float a3 = Qs[ty * 4 + 3][kk];
            unsigned long long b0 = *(const unsigned long long*)&KVs[kk][tx * 4];
            unsigned long long b1 = *(const unsigned long long*)&KVs[kk][tx * 4 + 2];
            unsigned long long av;
            av = pack2(a0, a0);
            acc[0][0] = fma2(av, b0, acc[0][0]); acc[0][1] = fma2(av, b1, acc[0][1]);
            av = pack2(a1, a1);
            acc[1][0] = fma2(av, b0, acc[1][0]); acc[1][1] = fma2(av, b1, acc[1][1]);
            av = pack2(a2, a2);
            acc[2][0] = fma2(av, b0, acc[2][0]); acc[2][1] = fma2(av, b1, acc[2][1]);
            av = pack2(a3, a3);
            acc[3][0] = fma2(av, b0, acc[3][0]); acc[3][1] = fma2(av, b1, acc[3][1]);
        }
    }

    float* op = out + ((size_t)b * LQ + l0 + ty * 4) * DQ + d0 + tx * 4;
#pragma unroll
    for (int r = 0; r < 4; r++) {
        float inv = 1.0f / g_norm[b * LQ + l0 + ty * 4 + r];
        float v0, v1, v2, v3;
        unpack2(acc[r][0], v0, v1);
        unpack2(acc[r][1], v2, v3);
        op[(size_t)r * DQ + 0] = v0 * inv;
        op[(size_t)r * DQ + 1] = v1 * inv;
        op[(size_t)r * DQ + 2] = v2 * inv;
        op[(size_t)r * DQ + 3] = v3 * inv;
    }
}

// ---------------------------------------------------------------------------
extern "C" void kernel_launch(void* const* d_in, const int* in_sizes, int n_in,
                              void* d_out, int out_size) {
    const float* queries = (const float*)d_in[0];
    const float* keys    = (const float*)d_in[1];
    const float* values  = (const float*)d_in[2];
    float* out = (float*)d_out;

    zero_kernel<<<(BQ * DQ * DQ + 255) / 256, 256>>>();
    ksum_kernel<<<dim3(32, BQ), 256>>>(keys);
    kvs_kernel<<<dim3(16, 4, BQ), 256>>>(keys, values);
    norm_kernel<<<dim3(LQ / 8, BQ), 256>>>(queries);
    out_kernel<<<dim3(LQ / 64, 4, BQ), 256>>>(queries, out);
}

// round 4
// speedup vs baseline: 2.6026x; 2.5908x over previous
#include <cuda_runtime.h>
#include <cstdint>

#define B_ 8
#define L_ 8192
#define D_ 256

__device__ float g_kvs[B_ * D_ * D_];   // [b][m][d]
__device__ float g_ksum[B_ * D_];       // [b][m]
__device__ float g_norm[B_ * L_];       // [b][l]

__device__ __forceinline__ float relu_eps(float x) { return fmaxf(x, 0.0f) + 1e-3f; }

__device__ __forceinline__ float cvt_tf32(float x) {
    uint32_t u;
    asm("cvt.rna.tf32.f32 %0, %1;" : "=r"(u) : "f"(x));
    return __uint_as_float(u);
}

__device__ __forceinline__ uint32_t smem_u32(const void* p) {
    uint32_t a;
    asm("{ .reg .u64 t; cvta.to.shared.u64 t, %1; cvt.u32.u64 %0, t; }" : "=r"(a) : "l"(p));
    return a;
}
__device__ __forceinline__ void cpa16(uint32_t s, const void* g) {
    asm volatile("cp.async.cg.shared.global [%0], [%1], 16;" :: "r"(s), "l"(g));
}
#define CP_COMMIT() asm volatile("cp.async.commit_group;" ::: "memory")
#define CP_WAIT1()  asm volatile("cp.async.wait_group 1;" ::: "memory")
#define CP_WAIT0()  asm volatile("cp.async.wait_group 0;" ::: "memory")

// m16n8k8 tf32 MMA, D += A*B.  A frag: a0=(g,t) a1=(g+8,t) a2=(g,t+4) a3=(g+8,t+4);
// B frag: b0=(k=t,n=g) b1=(k=t+4,n=g); C: c0=(g,2t) c1=(g,2t+1) c2=(g+8,2t) c3=(g+8,2t+1)
__device__ __forceinline__ void mma8(float* c, const uint32_t* a, const uint32_t* b) {
    asm volatile("mma.sync.aligned.m16n8k8.row.col.f32.tf32.tf32.f32 "
        "{%0,%1,%2,%3}, {%4,%5,%6,%7}, {%8,%9}, {%0,%1,%2,%3};"
        : "+f"(c[0]), "+f"(c[1]), "+f"(c[2]), "+f"(c[3])
        : "r"(a[0]), "r"(a[1]), "r"(a[2]), "r"(a[3]), "r"(b[0]), "r"(b[1]));
}

#define TSTR 132   // padded stride for [32][128] tiles (floats)
#define QSTR 36    // padded stride for [128][32] Q tiles (floats)

// ---------------------------------------------------------------------------
__global__ void zero_kernel() {
    int i = blockIdx.x * 256 + threadIdx.x;
    if (i < B_ * D_ * D_) g_kvs[i] = 0.0f;
    if (i < B_ * D_) g_ksum[i] = 0.0f;
}

// ---------------------------------------------------------------------------
// Pass 1: kvs[b][m][d] += sum_l relu'(K[l][m]) * V[l][d]   (+ fused ksum)
// grid (4 = 2 mtiles x 2 dtiles, 8 lchunks, B), 256 thr. CTA tile 128x128, K=1024.
// smem: K tiles [2][32][TSTR] + V tiles [2][32][TSTR]
#define P1_SMEM (4 * 32 * TSTR * 4)

__global__ void __launch_bounds__(256) pass1_mma(const float* __restrict__ K,
                                                 const float* __restrict__ V) {
    extern __shared__ float sm[];
    const int t = threadIdx.x, lane = t & 31, w = t >> 5;
    const int g = lane >> 2, tg = lane & 3;
    const int m0 = (blockIdx.x & 1) * 128, d0 = (blockIdx.x >> 1) * 128;
    const int b = blockIdx.z;
    const int lbase = blockIdx.y * 1024;
    const int wm = (w >> 2) * 64, wd = (w & 3) * 32;
    const bool do_ksum = (blockIdx.x >> 1) == 0;

    float acc[4][4][4] = {};
    float4 ksa = {0.f, 0.f, 0.f, 0.f};

    const uint32_t sb = smem_u32(sm);
    const float* Kg = K + (size_t)b * L_ * D_ + m0;
    const float* Vg = V + (size_t)b * L_ * D_ + d0;

    // prefetch helper (8 cps/thread: 4 K-chunks + 4 V-chunks)
    auto prefetch = [&](int s) {
        int buf = s & 1;
        uint32_t kb = sb + (uint32_t)(buf * 32 * TSTR) * 4;
        uint32_t vb = sb + (uint32_t)((2 + buf) * 32 * TSTR) * 4;
        const float* kg = Kg + (size_t)(lbase + s * 32) * D_;
        const float* vg = Vg + (size_t)(lbase + s * 32) * D_;
#pragma unroll
        for (int i = 0; i < 4; i++) {
            int j = t + i * 256, row = j >> 5, c = j & 31;
            uint32_t off = (uint32_t)(row * TSTR + c * 4) * 4;
            cpa16(kb + off, kg + (size_t)row * D_ + c * 4);
            cpa16(vb + off, vg + (size_t)row * D_ + c * 4);
        }
        CP_COMMIT();
    };

    prefetch(0);
    prefetch(1);

    const int S = 32;
    for (int s = 0; s < S; s++) {
        int buf = s & 1;
        if (s == S - 1) { CP_WAIT0(); } else { CP_WAIT1(); }
        // convert own chunks in place: K -> relu+tf32, V -> tf32
        float* Kb = sm + buf * 32 * TSTR;
        float* Vb = sm + (2 + buf) * 32 * TSTR;
#pragma unroll
        for (int i = 0; i < 4; i++) {
            int j = t + i * 256, row = j >> 5, c = j & 31;
            float4* kp = (float4*)&Kb[row * TSTR + c * 4];
            float4 kv = *kp;
            kv.x = cvt_tf32(relu_eps(kv.x)); kv.y = cvt_tf32(relu_eps(kv.y));
            kv.z = cvt_tf32(relu_eps(kv.z)); kv.w = cvt_tf32(relu_eps(kv.w));
            *kp = kv;
            float4* vp = (float4*)&Vb[row * TSTR + c * 4];
            float4 vv = *vp;
            vv.x = cvt_tf32(vv.x); vv.y = cvt_tf32(vv.y);
            vv.z = cvt_tf32(vv.z); vv.w = cvt_tf32(vv.w);
            *vp = vv;
        }
        __syncthreads();

        if (do_ksum && t < 32) {
#pragma unroll 8
            for (int l = 0; l < 32; l++) {
                float4 v = *(const float4*)&Kb[l * TSTR + t * 4];
                ksa.x += v.x; ksa.y += v.y; ksa.z += v.z; ksa.w += v.w;
            }
        }

        const uint32_t* Ku = (const uint32_t*)Kb;
        const uint32_t* Vu = (const uint32_t*)Vb;
#pragma unroll
        for (int kk8 = 0; kk8 < 4; kk8++) {
            int r0 = (kk8 * 8 + tg) * TSTR, r1 = r0 + 4 * TSTR;
            uint32_t a[4][4], bf[4][2];
#pragma unroll
            for (int mi = 0; mi < 4; mi++) {
                int col = wm + mi * 16 + g;
                a[mi][0] = Ku[r0 + col];
                a[mi][1] = Ku[r0 + col + 8];
                a[mi][2] = Ku[r1 + col];
                a[mi][3] = Ku[r1 + col + 8];
            }
#pragma unroll
            for (int ni = 0; ni < 4; ni++) {
                int col = wd + ni * 8 + g;
                bf[ni][0] = Vu[r0 + col];
                bf[ni][1] = Vu[r1 + col];
            }
#pragma unroll
            for (int mi = 0; mi < 4; mi++)
#pragma unroll
                for (int ni = 0; ni < 4; ni++) mma8(acc[mi][ni], a[mi], bf[ni]);
        }
        __syncthreads();
        if (s + 2 < S) prefetch(s + 2);
    }

    if (do_ksum && t < 32) {
        float* kp = &g_ksum[b * D_ + m0 + t * 4];
        atomicAdd(kp + 0, ksa.x); atomicAdd(kp + 1, ksa.y);
        atomicAdd(kp + 2, ksa.z); atomicAdd(kp + 3, ksa.w);
    }

#pragma unroll
    for (int mi = 0; mi < 4; mi++) {
        int mrow = m0 + wm + mi * 16 + g;
#pragma unroll
        for (int ni = 0; ni < 4; ni++) {
            int dcol = d0 + wd + ni * 8 + 2 * tg;
            float* p = &g_kvs[((size_t)b * D_ + mrow) * D_ + dcol];
            atomicAdd(p, acc[mi][ni][0]);
            atomicAdd(p + 1, acc[mi][ni][1]);
            atomicAdd(p + 8 * D_, acc[mi][ni][2]);
            atomicAdd(p + 8 * D_ + 1, acc[mi][ni][3]);
        }
    }
}

// ---------------------------------------------------------------------------
// norm[b][l] = sum_m tf32(relu'(Q[l][m])) * ksum[m]
__global__ void __launch_bounds__(256) norm_kernel(const float* __restrict__ queries) {
    int b = blockIdx.y, warp = threadIdx.x >> 5, lane = threadIdx.x & 31;
    int l = blockIdx.x * 8 + warp;
    const float* qp = queries + ((size_t)b * L_ + l) * D_;
    const float* ks = g_ksum + b * D_;
    float s = 0.0f;
#pragma unroll
    for (int m = lane; m < D_; m += 32) s += cvt_tf32(relu_eps(qp[m])) * ks[m];
#pragma unroll
    for (int o = 16; o > 0; o >>= 1) s += __shfl_xor_sync(0xffffffffu, s, o);
    if (lane == 0) g_norm[b * L_ + l] = s;
}

// ---------------------------------------------------------------------------
// Pass 2: out[l][d] = (sum_m relu'(Q[l][m]) * kvs[m][d]) / norm[l]
// grid (64 ltiles, 2 dtiles, B), 256 thr. CTA tile 128l x 128d, K=256.
// smem: Q tiles [2][128][QSTR] + KV tiles [2][32][TSTR]
#define P2_SMEM ((2 * 128 * QSTR + 2 * 32 * TSTR) * 4)

__global__ void __launch_bounds__(256) pass2_mma(const float* __restrict__ Q,
                                                 float* __restrict__ out) {
    extern __shared__ float sm[];
    const int t = threadIdx.x, lane = t & 31, w = t >> 5;
    const int g = lane >> 2, tg = lane & 3;
    const int b = blockIdx.z;
    const int l0 = blockIdx.x * 128, d0 = blockIdx.y * 128;
    const int wl = (w >> 2) * 64, wd = (w & 3) * 32;
    const int KVOFF = 2 * 128 * QSTR;

    float acc[4][4][4] = {};
    const uint32_t sb = smem_u32(sm);
    const float* Qg = Q + ((size_t)b * L_ + l0) * D_;
    const float* KVg = g_kvs + (size_t)b * D_ * D_ + d0;

    auto prefetch = [&](int s) {
        int buf = s & 1;
        uint32_t qb = sb + (uint32_t)(buf * 128 * QSTR) * 4;
        uint32_t kb = sb + (uint32_t)(KVOFF + buf * 32 * TSTR) * 4;
        int mb = s * 32;
#pragma unroll
        for (int i = 0; i < 4; i++) {
            int j = t + i * 256;
            int qrow = j >> 3, qc = j & 7;
            cpa16(qb + (uint32_t)(qrow * QSTR + qc * 4) * 4,
                  Qg + (size_t)qrow * D_ + mb + qc * 4);
            int krow = j >> 5, kc = j & 31;
            cpa16(kb + (uint32_t)(krow * TSTR + kc * 4) * 4,
                  KVg + (size_t)(mb + krow) * D_ + kc * 4);
        }
        CP_COMMIT();
    };

    prefetch(0);
    prefetch(1);

    const int S = 8;
    for (int s = 0; s < S; s++) {
        int buf = s & 1;
        if (s == S - 1) { CP_WAIT0(); } else { CP_WAIT1(); }
        float* Qb = sm + buf * 128 * QSTR;
        float* Kb = sm + KVOFF + buf * 32 * TSTR;
#pragma unroll
        for (int i = 0; i < 4; i++) {
            int j = t + i * 256;
            float4* qp = (float4*)&Qb[(j >> 3) * QSTR + (j & 7) * 4];
            float4 qv = *qp;
            qv.x = cvt_tf32(relu_eps(qv.x)); qv.y = cvt_tf32(relu_eps(qv.y));
            qv.z = cvt_tf32(relu_eps(qv.z)); qv.w = cvt_tf32(relu_eps(qv.w));
            *qp = qv;
            float4* kp = (float4*)&Kb[(j >> 5) * TSTR + (j & 31) * 4];
            float4 kv = *kp;
            kv.x = cvt_tf32(kv.x); kv.y = cvt_tf32(kv.y);
            kv.z = cvt_tf32(kv.z); kv.w = cvt_tf32(kv.w);
            *kp = kv;
        }
        __syncthreads();

        const uint32_t* Qu = (const uint32_t*)Qb;
        const uint32_t* Ku = (const uint32_t*)Kb;
#pragma unroll
        for (int kk8 = 0; kk8 < 4; kk8++) {
            int kc0 = kk8 * 8 + tg;
            uint32_t a[4][4], bf[4][2];
#pragma unroll
            for (int mi = 0; mi < 4; mi++) {
                int row = (wl + mi * 16 + g) * QSTR;
                a[mi][0] = Qu[row + kc0];
                a[mi][1] = Qu[row + 8 * QSTR + kc0];
                a[mi][2] = Qu[row + kc0 + 4];
                a[mi][3] = Qu[row + 8 * QSTR + kc0 + 4];
            }
            int r0 = kc0 * TSTR, r1 = r0 + 4 * TSTR;
#pragma unroll
            for (int ni = 0; ni < 4; ni++) {
                int col = wd + ni * 8 + g;
                bf[ni][0] = Ku[r0 + col];
                bf[ni][1] = Ku[r1 + col];
            }
#pragma unroll
            for (int mi = 0; mi < 4; mi++)
#pragma unroll
                for (int ni = 0; ni < 4; ni++) mma8(acc[mi][ni], a[mi], bf[ni]);
        }
        __syncthreads();
        if (s + 2 < S) prefetch(s + 2);
    }

#pragma unroll
    for (int mi = 0; mi < 4; mi++) {
        int lr = l0 + wl + mi * 16 + g;
        float inv0 = 1.0f / g_norm[b * L_ + lr];
        float inv1 = 1.0f / g_norm[b * L_ + lr + 8];
#pragma unroll
        for (int ni = 0; ni < 4; ni++) {
            int dcol = d0 + wd + ni * 8 + 2 * tg;
            float2 v0 = {acc[mi][ni][0] * inv0, acc[mi][ni][1] * inv0};
            float2 v1 = {acc[mi][ni][2] * inv1, acc[mi][ni][3] * inv1};
            *(float2*)&out[((size_t)b * L_ + lr) * D_ + dcol] = v0;
            *(float2*)&out[((size_t)b * L_ + lr + 8) * D_ + dcol] = v1;
        }
    }
}

// ---------------------------------------------------------------------------
extern "C" void kernel_launch(void* const* d_in, const int* in_sizes, int n_in,
                              void* d_out, int out_size) {
    const float* queries = (const float*)d_in[0];
    const float* keys    = (const float*)d_in[1];
    const float* values  = (const float*)d_in[2];
    float* out = (float*)d_out;

    cudaFuncSetAttribute(pass1_mma, cudaFuncAttributeMaxDynamicSharedMemorySize, P1_SMEM);
    cudaFuncSetAttribute(pass2_mma, cudaFuncAttributeMaxDynamicSharedMemorySize, P2_SMEM);

    zero_kernel<<<(B_ * D_ * D_ + 255) / 256, 256>>>();
    pass1_mma<<<dim3(4, 8, B_), 256, P1_SMEM>>>(keys, values);
    norm_kernel<<<dim3(L_ / 8, B_), 256>>>(queries);
    pass2_mma<<<dim3(L_ / 128, 2, B_), 256, P2_SMEM>>>(queries, out);
}

// round 5
// speedup vs baseline: 2.7918x; 1.0727x over previous
#include <cuda_runtime.h>
#include <cstdint>

#define B_ 8
#define L_ 8192
#define D_ 256

__device__ float g_kvsT[B_ * D_ * D_];  // [b][d][m]  (transposed!)
__device__ float g_ksum[B_ * D_];       // [b][m]

__device__ __forceinline__ float relu_eps(float x) { return fmaxf(x, 0.0f) + 1e-3f; }
__device__ __forceinline__ float cvt_tf32(float x) {
    uint32_t u;
    asm("cvt.rna.tf32.f32 %0, %1;" : "=r"(u) : "f"(x));
    return __uint_as_float(u);
}
__device__ __forceinline__ uint32_t smem_u32(const void* p) {
    uint32_t a;
    asm("{ .reg .u64 t; cvta.to.shared.u64 t, %1; cvt.u32.u64 %0, t; }" : "=r"(a) : "l"(p));
    return a;
}
__device__ __forceinline__ void cpa16(uint32_t s, const void* g) {
    asm volatile("cp.async.cg.shared.global [%0], [%1], 16;" :: "r"(s), "l"(g));
}
#define CP_COMMIT() asm volatile("cp.async.commit_group;" ::: "memory")
#define CP_WAIT1()  asm volatile("cp.async.wait_group 1;" ::: "memory")
#define CP_WAIT0()  asm volatile("cp.async.wait_group 0;" ::: "memory")

__device__ __forceinline__ void mma8(float* c, const uint32_t* a, const uint32_t* b) {
    asm volatile("mma.sync.aligned.m16n8k8.row.col.f32.tf32.tf32.f32 "
        "{%0,%1,%2,%3}, {%4,%5,%6,%7}, {%8,%9}, {%0,%1,%2,%3};"
        : "+f"(c[0]), "+f"(c[1]), "+f"(c[2]), "+f"(c[3])
        : "r"(a[0]), "r"(a[1]), "r"(a[2]), "r"(a[3]), "r"(b[0]), "r"(b[1]));
}
#define LDSM4(r0, r1, r2, r3, a) \
    asm volatile("ldmatrix.sync.aligned.m8n8.x4.shared.b16 {%0,%1,%2,%3}, [%4];" \
        : "=r"(r0), "=r"(r1), "=r"(r2), "=r"(r3) : "r"(a))

#define TSTR 132   // [32][128] tiles (pass1)
#define QSTR 36    // [128][32] tiles (pass2)

// ---------------------------------------------------------------------------
__global__ void zero_kernel() {
    int i = blockIdx.x * 256 + threadIdx.x;
    if (i < B_ * D_ * D_) g_kvsT[i] = 0.0f;
    if (i < B_ * D_) g_ksum[i] = 0.0f;
}

// ---------------------------------------------------------------------------
// Pass 1: kvsT[b][d][m] += sum_l relu'(K[l][m]) * V[l][d]   (+ fused ksum)
// grid (4, 8 lchunks, B), 256 thr, CTA tile 128m x 128d, K=1024.
#define P1_SMEM (4 * 32 * TSTR * 4)

__global__ void __launch_bounds__(256) pass1_mma(const float* __restrict__ K,
                                                 const float* __restrict__ V) {
    extern __shared__ float sm[];
    const int t = threadIdx.x, lane = t & 31, w = t >> 5;
    const int g = lane >> 2, tg = lane & 3;
    const int m0 = (blockIdx.x & 1) * 128, d0 = (blockIdx.x >> 1) * 128;
    const int b = blockIdx.z;
    const int lbase = blockIdx.y * 1024;
    const int wm = (w >> 2) * 64, wd = (w & 3) * 32;
    const bool do_ksum = (blockIdx.x >> 1) == 0;

    float acc[4][4][4] = {};
    float4 ksa = {0.f, 0.f, 0.f, 0.f};

    const uint32_t sb = smem_u32(sm);
    const float* Kg = K + (size_t)b * L_ * D_ + m0;
    const float* Vg = V + (size_t)b * L_ * D_ + d0;

    auto prefetch = [&](int s) {
        int buf = s & 1;
        uint32_t kb = sb + (uint32_t)(buf * 32 * TSTR) * 4;
        uint32_t vb = sb + (uint32_t)((2 + buf) * 32 * TSTR) * 4;
        const float* kg = Kg + (size_t)(lbase + s * 32) * D_;
        const float* vg = Vg + (size_t)(lbase + s * 32) * D_;
#pragma unroll
        for (int i = 0; i < 4; i++) {
            int j = t + i * 256, row = j >> 5, c = j & 31;
            uint32_t off = (uint32_t)(row * TSTR + c * 4) * 4;
            cpa16(kb + off, kg + (size_t)row * D_ + c * 4);
            cpa16(vb + off, vg + (size_t)row * D_ + c * 4);
        }
        CP_COMMIT();
    };

    prefetch(0);
    prefetch(1);

    const int S = 32;
    for (int s = 0; s < S; s++) {
        int buf = s & 1;
        if (s == S - 1) { CP_WAIT0(); } else { CP_WAIT1(); }
        float* Kb = sm + buf * 32 * TSTR;
        float* Vb = sm + (2 + buf) * 32 * TSTR;
        // K sweep only: relu + rna-tf32 (V fed raw; HW truncates to tf32)
#pragma unroll
        for (int i = 0; i < 4; i++) {
            int j = t + i * 256, row = j >> 5, c = j & 31;
            float4* kp = (float4*)&Kb[row * TSTR + c * 4];
            float4 kv = *kp;
            kv.x = cvt_tf32(relu_eps(kv.x)); kv.y = cvt_tf32(relu_eps(kv.y));
            kv.z = cvt_tf32(relu_eps(kv.z)); kv.w = cvt_tf32(relu_eps(kv.w));
            *kp = kv;
        }
        __syncthreads();

        if (do_ksum && t < 32) {
#pragma unroll 8
            for (int l = 0; l < 32; l++) {
                float4 v = *(const float4*)&Kb[l * TSTR + t * 4];
                ksa.x += v.x; ksa.y += v.y; ksa.z += v.z; ksa.w += v.w;
            }
        }

        const uint32_t* Ku = (const uint32_t*)Kb;
        const uint32_t* Vu = (const uint32_t*)Vb;
#pragma unroll
        for (int kk8 = 0; kk8 < 4; kk8++) {
            int r0 = (kk8 * 8 + tg) * TSTR, r1 = r0 + 4 * TSTR;
            uint32_t a[4][4], bf[4][2];
#pragma unroll
            for (int mi = 0; mi < 4; mi++) {
                int col = wm + mi * 16 + g;
                a[mi][0] = Ku[r0 + col];
                a[mi][1] = Ku[r0 + col + 8];
                a[mi][2] = Ku[r1 + col];
                a[mi][3] = Ku[r1 + col + 8];
            }
#pragma unroll
            for (int ni = 0; ni < 4; ni++) {
                int col = wd + ni * 8 + g;
                bf[ni][0] = Vu[r0 + col];
                bf[ni][1] = Vu[r1 + col];
            }
#pragma unroll
            for (int mi = 0; mi < 4; mi++)
#pragma unroll
                for (int ni = 0; ni < 4; ni++) mma8(acc[mi][ni], a[mi], bf[ni]);
        }
        __syncthreads();
        if (s + 2 < S) prefetch(s + 2);
    }

    if (do_ksum && t < 32) {
        float* kp = &g_ksum[b * D_ + m0 + t * 4];
        atomicAdd(kp + 0, ksa.x); atomicAdd(kp + 1, ksa.y);
        atomicAdd(kp + 2, ksa.z); atomicAdd(kp + 3, ksa.w);
    }

    // transposed epilogue into kvsT[d][m]
#pragma unroll
    for (int mi = 0; mi < 4; mi++) {
        int mrow = m0 + wm + mi * 16 + g;
#pragma unroll
        for (int ni = 0; ni < 4; ni++) {
            int dcol = d0 + wd + ni * 8 + 2 * tg;
            float* base = &g_kvsT[(size_t)b * D_ * D_];
            atomicAdd(base + (size_t)dcol * D_ + mrow, acc[mi][ni][0]);
            atomicAdd(base + (size_t)(dcol + 1) * D_ + mrow, acc[mi][ni][1]);
            atomicAdd(base + (size_t)dcol * D_ + mrow + 8, acc[mi][ni][2]);
            atomicAdd(base + (size_t)(dcol + 1) * D_ + mrow + 8, acc[mi][ni][3]);
        }
    }
}

// ---------------------------------------------------------------------------
// Pass 2: out[l][d] = (sum_m q'[l][m] * kvsT[d][m]) / (sum_m q'[l][m] * ksum[m])
// grid (64 ltiles, 2 dtiles, B), 256 thr. CTA tile 128l x 128d, K=256.
// smem: Q [2][128][QSTR] + KVT [2][128][QSTR] + norm[128]
#define KVOFF (2 * 128 * QSTR)
#define NRMOFF (KVOFF + 2 * 128 * QSTR)
#define P2_SMEM ((NRMOFF + 128) * 4)

__global__ void __launch_bounds__(256) pass2_mma(const float* __restrict__ Q,
                                                 float* __restrict__ out) {
    extern __shared__ float sm[];
    const int t = threadIdx.x, lane = t & 31, w = t >> 5;
    const int g = lane >> 2, tg = lane & 3;
    const int b = blockIdx.z;
    const int l0 = blockIdx.x * 128, d0 = blockIdx.y * 128;
    const int wl = (w >> 2) * 64, wd = (w & 3) * 32;
    float* norm_s = sm + NRMOFF;

    float acc[4][4][4] = {};
    const uint32_t sb = smem_u32(sm);
    const float* Qg = Q + ((size_t)b * L_ + l0) * D_;
    const float* KVg = g_kvsT + ((size_t)b * D_ + d0) * D_;
    const float* ksg = g_ksum + b * D_;

    if (t < 128) norm_s[t] = 0.0f;

    auto prefetch = [&](int s) {
        int buf = s & 1;
        uint32_t qb = sb + (uint32_t)(buf * 128 * QSTR) * 4;
        uint32_t kb = sb + (uint32_t)(KVOFF + buf * 128 * QSTR) * 4;
        int mb = s * 32;
#pragma unroll
        for (int i = 0; i < 4; i++) {
            int j = t + i * 256, row = j >> 3, c = j & 7;
            uint32_t off = (uint32_t)(row * QSTR + c * 4) * 4;
            cpa16(qb + off, Qg + (size_t)row * D_ + mb + c * 4);
            cpa16(kb + off, KVg + (size_t)row * D_ + mb + c * 4);
        }
        CP_COMMIT();
    };

    prefetch(0);
    prefetch(1);
    __syncthreads();  // norm_s zeroed before any atomic

    // per-lane ldmatrix base offsets (bytes, within a buffer)
    uint32_t qa_off[4], ba_off[2];
#pragma unroll
    for (int mi = 0; mi < 4; mi++)
        qa_off[mi] = (uint32_t)(((wl + mi * 16 + (lane & 15)) * QSTR + (lane >> 4) * 4) * 4);
#pragma unroll
    for (int nj = 0; nj < 2; nj++)
        ba_off[nj] = (uint32_t)(((wd + nj * 16 + (lane & 7) + ((lane >> 4) << 3)) * QSTR +
                                 (((lane >> 3) & 1) << 2)) * 4);

    const int S = 8;
    for (int s = 0; s < S; s++) {
        int buf = s & 1;
        if (s == S - 1) { CP_WAIT0(); } else { CP_WAIT1(); }
        float* Qb = sm + buf * 128 * QSTR;
        int mb = s * 32;
        // Q sweep: relu+tf32 in place, fused norm partial (KV fed raw)
#pragma unroll
        for (int i = 0; i < 4; i++) {
            int j = t + i * 256, row = j >> 3, c = j & 7;
            float4* qp = (float4*)&Qb[row * QSTR + c * 4];
            float4 qv = *qp;
            qv.x = cvt_tf32(relu_eps(qv.x)); qv.y = cvt_tf32(relu_eps(qv.y));
            qv.z = cvt_tf32(relu_eps(qv.z)); qv.w = cvt_tf32(relu_eps(qv.w));
            *qp = qv;
            float4 ks = *(const float4*)(ksg + mb + c * 4);
            float r = qv.x * ks.x + qv.y * ks.y + qv.z * ks.z + qv.w * ks.w;
            r += __shfl_xor_sync(0xffffffffu, r, 1);
            r += __shfl_xor_sync(0xffffffffu, r, 2);
            r += __shfl_xor_sync(0xffffffffu, r, 4);
            if ((lane & 7) == 0) atomicAdd(&norm_s[row], r);
        }
        __syncthreads();

        uint32_t qbase = sb + (uint32_t)(buf * 128 * QSTR) * 4;
        uint32_t kbase = sb + (uint32_t)(KVOFF + buf * 128 * QSTR) * 4;
#pragma unroll
        for (int kk8 = 0; kk8 < 4; kk8++) {
            uint32_t a[4][4], bf[4][2];
#pragma unroll
            for (int mi = 0; mi < 4; mi++)
                LDSM4(a[mi][0], a[mi][1], a[mi][2], a[mi][3], qbase + qa_off[mi] + kk8 * 32);
#pragma unroll
            for (int nj = 0; nj < 2; nj++)
                LDSM4(bf[2 * nj][0], bf[2 * nj][1], bf[2 * nj + 1][0], bf[2 * nj + 1][1],
                      kbase + ba_off[nj] + kk8 * 32);
#pragma unroll
            for (int mi = 0; mi < 4; mi++)
#pragma unroll
                for (int ni = 0; ni < 4; ni++) mma8(acc[mi][ni], a[mi], bf[ni]);
        }
        __syncthreads();
        if (s + 2 < S) prefetch(s + 2);
    }

#pragma unroll
    for (int mi = 0; mi < 4; mi++) {
        int lloc = wl + mi * 16 + g;
        float inv0 = 1.0f / norm_s[lloc];
        float inv1 = 1.0f / norm_s[lloc + 8];
        int lr = l0 + lloc;
#pragma unroll
        for (int ni = 0; ni < 4; ni++) {
            int dcol = d0 + wd + ni * 8 + 2 * tg;
            float2 v0 = {acc[mi][ni][0] * inv0, acc[mi][ni][1] * inv0};
            float2 v1 = {acc[mi][ni][2] * inv1, acc[mi][ni][3] * inv1};
            *(float2*)&out[((size_t)b * L_ + lr) * D_ + dcol] = v0;
            *(float2*)&out[((size_t)b * L_ + lr + 8) * D_ + dcol] = v1;
        }
    }
}

// ---------------------------------------------------------------------------
extern "C" void kernel_launch(void* const* d_in, const int* in_sizes, int n_in,
                              void* d_out, int out_size) {
    const float* queries = (const float*)d_in[0];
    const float* keys    = (const float*)d_in[1];
    const float* values  = (const float*)d_in[2];
    float* out = (float*)d_out;

    cudaFuncSetAttribute(pass1_mma, cudaFuncAttributeMaxDynamicSharedMemorySize, P1_SMEM);
    cudaFuncSetAttribute(pass2_mma, cudaFuncAttributeMaxDynamicSharedMemorySize, P2_SMEM);

    zero_kernel<<<(B_ * D_ * D_ + 255) / 256, 256>>>();
    pass1_mma<<<dim3(4, 8, B_), 256, P1_SMEM>>>(keys, values);
    pass2_mma<<<dim3(L_ / 128, 2, B_), 256, P2_SMEM>>>(queries, out);
}

// round 6
// speedup vs baseline: 3.4507x; 1.2360x over previous
#include <cuda_runtime.h>
#include <cstdint>

#define B_ 8
#define L_ 8192
#define D_ 256

__device__ float g_kvsT[B_ * D_ * D_];  // [b][d][m]
__device__ float g_ksum[B_ * D_];       // [b][m]

__device__ __forceinline__ float relu_eps(float x) { return fmaxf(x, 0.0f) + 1e-3f; }
__device__ __forceinline__ float cvt_tf32(float x) {
    uint32_t u;
    asm("cvt.rna.tf32.f32 %0, %1;" : "=r"(u) : "f"(x));
    return __uint_as_float(u);
}
__device__ __forceinline__ uint32_t smem_u32(const void* p) {
    uint32_t a;
    asm("{ .reg .u64 t; cvta.to.shared.u64 t, %1; cvt.u32.u64 %0, t; }" : "=r"(a) : "l"(p));
    return a;
}
__device__ __forceinline__ void cpa16(uint32_t s, const void* g) {
    asm volatile("cp.async.cg.shared.global [%0], [%1], 16;" :: "r"(s), "l"(g));
}
#define CP_COMMIT() asm volatile("cp.async.commit_group;" ::: "memory")
#define CP_WAIT1()  asm volatile("cp.async.wait_group 1;" ::: "memory")
#define CP_WAIT0()  asm volatile("cp.async.wait_group 0;" ::: "memory")

__device__ __forceinline__ void mma8(float* c, const uint32_t* a, const uint32_t* b) {
    asm volatile("mma.sync.aligned.m16n8k8.row.col.f32.tf32.tf32.f32 "
        "{%0,%1,%2,%3}, {%4,%5,%6,%7}, {%8,%9}, {%0,%1,%2,%3};"
        : "+f"(c[0]), "+f"(c[1]), "+f"(c[2]), "+f"(c[3])
        : "r"(a[0]), "r"(a[1]), "r"(a[2]), "r"(a[3]), "r"(b[0]), "r"(b[1]));
}

#define TSTR 136   // pass1 [32 l][128] tiles; bank = 8*tg+g -> conflict-free
#define QSTR 36    // pass2 [128][32 k] tiles; bank = 4*g+tg -> conflict-free

// ---------------------------------------------------------------------------
__global__ void zero_kernel() {
    int i = blockIdx.x * 256 + threadIdx.x;
    if (i < B_ * D_ * D_) g_kvsT[i] = 0.0f;
    if (i < B_ * D_) g_ksum[i] = 0.0f;
}

// ---------------------------------------------------------------------------
// Pass 1: kvsT[b][d][m] += sum_l relu'(K[l][m]) * V[l][d]   (+ fused ksum)
// grid (4 = 2m x 2d, 8 lchunks, B), 128 thr (4 warps 2x2, warp tile 64m x 64d).
#define P1_SMEM (4 * 32 * TSTR * 4)

__global__ void __launch_bounds__(128) pass1_mma(const float* __restrict__ K,
                                                 const float* __restrict__ V) {
    extern __shared__ float sm[];
    const int t = threadIdx.x, lane = t & 31, w = t >> 5;
    const int g = lane >> 2, tg = lane & 3;
    const int m0 = (blockIdx.x & 1) * 128, d0 = (blockIdx.x >> 1) * 128;
    const int b = blockIdx.z;
    const int lbase = blockIdx.y * 1024;
    const int wm = (w & 1) * 64, wd = (w >> 1) * 64;
    const bool do_ksum = ((blockIdx.x >> 1) == 0) && ((w >> 1) == 0);

    float acc[4][8][4] = {};
    float ksA[4][2] = {};

    const uint32_t sb = smem_u32(sm);
    const float* Kg = K + (size_t)b * L_ * D_ + m0;
    const float* Vg = V + (size_t)b * L_ * D_ + d0;

    auto prefetch = [&](int s) {
        int buf = s & 1;
        uint32_t kb = sb + (uint32_t)(buf * 32 * TSTR) * 4;
        uint32_t vb = sb + (uint32_t)((2 + buf) * 32 * TSTR) * 4;
        const float* kg = Kg + (size_t)(lbase + s * 32) * D_;
        const float* vg = Vg + (size_t)(lbase + s * 32) * D_;
#pragma unroll
        for (int i = 0; i < 8; i++) {
            int j = t + i * 128, row = j >> 5, c = j & 31;
            uint32_t off = (uint32_t)(row * TSTR + c * 4) * 4;
            cpa16(kb + off, kg + (size_t)row * D_ + c * 4);
            cpa16(vb + off, vg + (size_t)row * D_ + c * 4);
        }
        CP_COMMIT();
    };

    prefetch(0);
    prefetch(1);

    const int S = 32;
    for (int s = 0; s < S; s++) {
        int buf = s & 1;
        if (s >= S - 2) { CP_WAIT0(); } else { CP_WAIT1(); }
        __syncthreads();
        const float* Kb = sm + buf * 32 * TSTR;
        const float* Vb = sm + (2 + buf) * 32 * TSTR;
#pragma unroll
        for (int kk8 = 0; kk8 < 4; kk8++) {
            int r0 = (kk8 * 8 + tg) * TSTR, r4 = r0 + 4 * TSTR;
            uint32_t Au[4][4];
#pragma unroll
            for (int mi = 0; mi < 4; mi++) {
                int col = wm + mi * 16 + g;
                float a0 = cvt_tf32(relu_eps(Kb[r0 + col]));
                float a1 = cvt_tf32(relu_eps(Kb[r0 + col + 8]));
                float a2 = cvt_tf32(relu_eps(Kb[r4 + col]));
                float a3 = cvt_tf32(relu_eps(Kb[r4 + col + 8]));
                ksA[mi][0] += a0 + a2;
                ksA[mi][1] += a1 + a3;
                Au[mi][0] = __float_as_uint(a0);
                Au[mi][1] = __float_as_uint(a1);
                Au[mi][2] = __float_as_uint(a2);
                Au[mi][3] = __float_as_uint(a3);
            }
            uint32_t Bf[8][2];
#pragma unroll
            for (int ni = 0; ni < 8; ni++) {
                int cn = wd + ni * 8 + g;
                Bf[ni][0] = __float_as_uint(cvt_tf32(Vb[r0 + cn]));
                Bf[ni][1] = __float_as_uint(cvt_tf32(Vb[r4 + cn]));
            }
#pragma unroll
            for (int mi = 0; mi < 4; mi++)
#pragma unroll
                for (int ni = 0; ni < 8; ni++) mma8(acc[mi][ni], Au[mi], Bf[ni]);
        }
        __syncthreads();
        if (s + 2 < S) prefetch(s + 2);
    }

    if (do_ksum) {
#pragma unroll
        for (int mi = 0; mi < 4; mi++) {
            float r0 = ksA[mi][0], r1 = ksA[mi][1];
            r0 += __shfl_xor_sync(0xffffffffu, r0, 1);
            r0 += __shfl_xor_sync(0xffffffffu, r0, 2);
            r1 += __shfl_xor_sync(0xffffffffu, r1, 1);
            r1 += __shfl_xor_sync(0xffffffffu, r1, 2);
            if (tg == 0) {
                atomicAdd(&g_ksum[b * D_ + m0 + wm + mi * 16 + g], r0);
                atomicAdd(&g_ksum[b * D_ + m0 + wm + mi * 16 + g + 8], r1);
            }
        }
    }

    float* base = &g_kvsT[(size_t)b * D_ * D_];
#pragma unroll
    for (int mi = 0; mi < 4; mi++) {
        int mrow = m0 + wm + mi * 16 + g;
#pragma unroll
        for (int ni = 0; ni < 8; ni++) {
            int dc = d0 + wd + ni * 8 + 2 * tg;
            atomicAdd(base + (size_t)dc * D_ + mrow, acc[mi][ni][0]);
            atomicAdd(base + (size_t)(dc + 1) * D_ + mrow, acc[mi][ni][1]);
            atomicAdd(base + (size_t)dc * D_ + mrow + 8, acc[mi][ni][2]);
            atomicAdd(base + (size_t)(dc + 1) * D_ + mrow + 8, acc[mi][ni][3]);
        }
    }
}

// ---------------------------------------------------------------------------
// Pass 2: out[l][d] = (sum_m q'[l][m] * kvsT[d][m]) / (sum_m q'[l][m] * ksum[m])
// grid (64 ltiles, 2 dtiles, B), 128 thr (4 warps 2x2, warp tile 64l x 64d).
#define P2_SMEM (4 * 128 * QSTR * 4)

__global__ void __launch_bounds__(128) pass2_mma(const float* __restrict__ Q,
                                                 float* __restrict__ out) {
    extern __shared__ float sm[];
    const int t = threadIdx.x, lane = t & 31, w = t >> 5;
    const int g = lane >> 2, tg = lane & 3;
    const int b = blockIdx.z;
    const int l0 = blockIdx.x * 128, d0 = blockIdx.y * 128;
    const int wl = (w & 1) * 64, wd = (w >> 1) * 64;

    float acc[4][8][4] = {};
    float nA[4] = {}, nB[4] = {};

    const uint32_t sb = smem_u32(sm);
    const float* Qg = Q + ((size_t)b * L_ + l0) * D_;
    const float* KVg = g_kvsT + ((size_t)b * D_ + d0) * D_;
    const float* ksg = g_ksum + b * D_;

    auto prefetch = [&](int s) {
        int buf = s & 1;
        uint32_t qb = sb + (uint32_t)(buf * 128 * QSTR) * 4;
        uint32_t kb = sb + (uint32_t)((2 + buf) * 128 * QSTR) * 4;
        int mb = s * 32;
#pragma unroll
        for (int i = 0; i < 8; i++) {
            int j = t + i * 128, row = j >> 3, c = j & 7;
            uint32_t off = (uint32_t)(row * QSTR + c * 4) * 4;
            cpa16(qb + off, Qg + (size_t)row * D_ + mb + c * 4);
            cpa16(kb + off, KVg + (size_t)row * D_ + mb + c * 4);
        }
        CP_COMMIT();
    };

    prefetch(0);
    prefetch(1);

    const int S = 8;
    for (int s = 0; s < S; s++) {
        int buf = s & 1;
        if (s >= S - 2) { CP_WAIT0(); } else { CP_WAIT1(); }
        __syncthreads();
        const float* Qb = sm + buf * 128 * QSTR;
        const float* Kb = sm + (2 + buf) * 128 * QSTR;
        int mb = s * 32;
#pragma unroll
        for (int kk8 = 0; kk8 < 4; kk8++) {
            int k0 = kk8 * 8;
            float ks0 = __ldg(ksg + mb + k0 + tg);
            float ks1 = __ldg(ksg + mb + k0 + tg + 4);
            uint32_t Au[4][4];
#pragma unroll
            for (int mi = 0; mi < 4; mi++) {
                int row = (wl + mi * 16 + g) * QSTR;
                float a0 = cvt_tf32(relu_eps(Qb[row + k0 + tg]));
                float a1 = cvt_tf32(relu_eps(Qb[row + 8 * QSTR + k0 + tg]));
                float a2 = cvt_tf32(relu_eps(Qb[row + k0 + tg + 4]));
                float a3 = cvt_tf32(relu_eps(Qb[row + 8 * QSTR + k0 + tg + 4]));
                nA[mi] += a0 * ks0 + a2 * ks1;
                nB[mi] += a1 * ks0 + a3 * ks1;
                Au[mi][0] = __float_as_uint(a0);
                Au[mi][1] = __float_as_uint(a1);
                Au[mi][2] = __float_as_uint(a2);
                Au[mi][3] = __float_as_uint(a3);
            }
            uint32_t Bf[8][2];
#pragma unroll
            for (int ni = 0; ni < 8; ni++) {
                int dn = (wd + ni * 8 + g) * QSTR;
                Bf[ni][0] = __float_as_uint(cvt_tf32(Kb[dn + k0 + tg]));
                Bf[ni][1] = __float_as_uint(cvt_tf32(Kb[dn + k0 + tg + 4]));
            }
#pragma unroll
            for (int mi = 0; mi < 4; mi++)
#pragma unroll
                for (int ni = 0; ni < 8; ni++) mma8(acc[mi][ni], Au[mi], Bf[ni]);
        }
        __syncthreads();
        if (s + 2 < S) prefetch(s + 2);
    }

#pragma unroll
    for (int mi = 0; mi < 4; mi++) {
        float r0 = nA[mi], r1 = nB[mi];
        r0 += __shfl_xor_sync(0xffffffffu, r0, 1);
        r0 += __shfl_xor_sync(0xffffffffu, r0, 2);
        r1 += __shfl_xor_sync(0xffffffffu, r1, 1);
        r1 += __shfl_xor_sync(0xffffffffu, r1, 2);
        float inv0 = 1.0f / r0, inv1 = 1.0f / r1;
        int lr = l0 + wl + mi * 16 + g;
#pragma unroll
        for (int ni = 0; ni < 8; ni++) {
            int dc = d0 + wd + ni * 8 + 2 * tg;
            float2 v0 = {acc[mi][ni][0] * inv0, acc[mi][ni][1] * inv0};
            float2 v1 = {acc[mi][ni][2] * inv1, acc[mi][ni][3] * inv1};
            *(float2*)&out[((size_t)b * L_ + lr) * D_ + dc] = v0;
            *(float2*)&out[((size_t)b * L_ + lr + 8) * D_ + dc] = v1;
        }
    }
}

// ---------------------------------------------------------------------------
extern "C" void kernel_launch(void* const* d_in, const int* in_sizes, int n_in,
                              void* d_out, int out_size) {
    const float* queries = (const float*)d_in[0];
    const float* keys    = (const float*)d_in[1];
    const float* values  = (const float*)d_in[2];
    float* out = (float*)d_out;

    cudaFuncSetAttribute(pass1_mma, cudaFuncAttributeMaxDynamicSharedMemorySize, P1_SMEM);
    cudaFuncSetAttribute(pass2_mma, cudaFuncAttributeMaxDynamicSharedMemorySize, P2_SMEM);

    zero_kernel<<<(B_ * D_ * D_ + 255) / 256, 256>>>();
    pass1_mma<<<dim3(4, 8, B_), 128, P1_SMEM>>>(keys, values);
    pass2_mma<<<dim3(L_ / 128, 2, B_), 128, P2_SMEM>>>(queries, out);
}